// round 4
// baseline (speedup 1.0000x reference)
#include <cuda_runtime.h>

#define H 128
#define NN 100000
#define NG 64

// ---------------- scratch (static device allocations; no runtime alloc) ----
__device__ __align__(16) float d_m[(size_t)NN * H];     // message GEMM output
__device__ __align__(16) float d_aggr[(size_t)NN * H];  // scatter-add accumulator
__device__ __align__(16) float d_hA[(size_t)NN * H];    // ping
__device__ __align__(16) float d_hB[(size_t)NN * H];    // pong
__device__ __align__(16) float d_gsum[NG * H];
__device__ float d_gcnt[NG];

__device__ __forceinline__ const float* pick_in(int sel, const float* x) {
    return sel == 0 ? x : (sel == 1 ? (const float*)d_hA : (const float*)d_hB);
}

// ---------------- zero the aggregation buffer ------------------------------
__global__ void zero_aggr_kernel() {
    int i = blockIdx.x * blockDim.x + threadIdx.x;  // exact: NN*H/4 elements
    ((float4*)d_aggr)[i] = make_float4(0.f, 0.f, 0.f, 0.f);
}

// ---------------- m = h @ W  ([N,128] x [128,128]) -------------------------
// Block: 64 rows x 128 cols, 256 threads, 4x8 register tile per thread.
// smem: sH[k][r] pitch 68 (transposed input), sW[k][c] pitch 132.
__global__ __launch_bounds__(256) void mgemm_kernel(
    const float* __restrict__ x, int hsel,
    const float* __restrict__ W, int nrows) {
    extern __shared__ float smem[];
    float* sH = smem;             // 128 x 68
    float* sW = smem + 128 * 68;  // 128 x 132

    const float* hin = pick_in(hsel, x);
    int t = threadIdx.x;
    int row0 = blockIdx.x * 64;

    // load h tile transposed
    for (int i = t; i < 64 * 32; i += 256) {
        int r = i >> 5, k4 = i & 31;
        float4 v = make_float4(0.f, 0.f, 0.f, 0.f);
        if (row0 + r < nrows)
            v = *(const float4*)(hin + (size_t)(row0 + r) * H + k4 * 4);
        sH[(k4 * 4 + 0) * 68 + r] = v.x;
        sH[(k4 * 4 + 1) * 68 + r] = v.y;
        sH[(k4 * 4 + 2) * 68 + r] = v.z;
        sH[(k4 * 4 + 3) * 68 + r] = v.w;
    }
    // load W directly ([k][c] row-major already)
    for (int i = t; i < 128 * 32; i += 256) {
        int k = i >> 5, c4 = i & 31;
        float4 v = *(const float4*)(W + (size_t)k * H + c4 * 4);
        *(float4*)&sW[k * 132 + c4 * 4] = v;
    }
    __syncthreads();

    int tr = t >> 4, tc = t & 15;
    int r0 = tr * 4, c0 = tc * 8;
    float acc[4][8];
#pragma unroll
    for (int i = 0; i < 4; i++)
#pragma unroll
        for (int j = 0; j < 8; j++) acc[i][j] = 0.f;

#pragma unroll 4
    for (int k = 0; k < 128; k++) {
        float4 a = *(const float4*)&sH[k * 68 + r0];
        float4 b0 = *(const float4*)&sW[k * 132 + c0];
        float4 b1 = *(const float4*)&sW[k * 132 + c0 + 4];
        float av[4] = {a.x, a.y, a.z, a.w};
        float bv[8] = {b0.x, b0.y, b0.z, b0.w, b1.x, b1.y, b1.z, b1.w};
#pragma unroll
        for (int i = 0; i < 4; i++)
#pragma unroll
            for (int j = 0; j < 8; j++) acc[i][j] += av[i] * bv[j];
    }

#pragma unroll
    for (int i = 0; i < 4; i++) {
        int r = row0 + r0 + i;
        if (r < nrows) {
            float4 o0 = make_float4(acc[i][0], acc[i][1], acc[i][2], acc[i][3]);
            float4 o1 = make_float4(acc[i][4], acc[i][5], acc[i][6], acc[i][7]);
            *(float4*)(d_m + (size_t)r * H + c0) = o0;
            *(float4*)(d_m + (size_t)r * H + c0 + 4) = o1;
        }
    }
}

// ---------------- scatter-add: aggr[dst] += m[src] -------------------------
// one warp per edge; 32 lanes x float4 = 128 floats; vector red to L2.
// edge_index delivered by the harness as int32 (int64 inputs are downcast).
__global__ __launch_bounds__(256) void scatter_kernel(
    const int* __restrict__ ei, int E) {
    int gw = (blockIdx.x * 256 + threadIdx.x) >> 5;
    if (gw >= E) return;
    int lane = threadIdx.x & 31;
    int s = __ldg(ei + gw);
    int d = __ldg(ei + E + gw);
    float4 v = *((const float4*)(d_m + (size_t)s * H) + lane);
    float4* p = (float4*)(d_aggr + (size_t)d * H) + lane;
    asm volatile("red.global.add.v4.f32 [%0], {%1,%2,%3,%4};"
                 :: "l"(p), "f"(v.x), "f"(v.y), "f"(v.z), "f"(v.w)
                 : "memory");
}

// ---------------- fused GRU cell -------------------------------------------
// h_new = (1-z)*n + z*h,  r=sig(aggr@Wir'+h@Whr'), z=..., n=tanh(i_n + r*h_n)
// Block: 64 rows, 256 threads, 4x8 tile. 3 stages (r, z, n); r,z kept in regs.
__global__ __launch_bounds__(256) void gru_kernel(
    const float* __restrict__ x, int hinsel, int houtsel,
    const float* __restrict__ w_ih, const float* __restrict__ w_hh,
    const float* __restrict__ b_ih, const float* __restrict__ b_hh,
    int nrows) {
    extern __shared__ float smem[];
    float* sA  = smem;                  // 128 x 68  (aggr^T)
    float* sHt = smem + 8704;           // 128 x 68  (h^T)
    float* sWi = smem + 17408;          // 128 x 132 (w_ih gate slice, [k][c])
    float* sWh = smem + 17408 + 16896;  // 128 x 132

    const float* hin = pick_in(hinsel, x);
    float* hout = (houtsel == 1) ? d_hA : d_hB;

    int t = threadIdx.x;
    int row0 = blockIdx.x * 64;

    // load aggr + h transposed
    for (int i = t; i < 64 * 32; i += 256) {
        int r = i >> 5, k4 = i & 31;
        float4 va = make_float4(0.f, 0.f, 0.f, 0.f), vh = va;
        if (row0 + r < nrows) {
            va = *(const float4*)(d_aggr + (size_t)(row0 + r) * H + k4 * 4);
            vh = *(const float4*)(hin + (size_t)(row0 + r) * H + k4 * 4);
        }
#pragma unroll
        for (int j = 0; j < 4; j++) {
            sA[(k4 * 4 + j) * 68 + r]  = (&va.x)[j];
            sHt[(k4 * 4 + j) * 68 + r] = (&vh.x)[j];
        }
    }

    int tr = t >> 4, tc = t & 15;
    int r0 = tr * 4, c0 = tc * 8;

    auto loadW = [&](int g) {
        for (int i = t; i < 128 * 32; i += 256) {
            int c = i >> 5, k4 = i & 31;
            float4 vi = *(const float4*)(w_ih + (size_t)(g * H + c) * H + k4 * 4);
            float4 vh = *(const float4*)(w_hh + (size_t)(g * H + c) * H + k4 * 4);
#pragma unroll
            for (int j = 0; j < 4; j++) {
                sWi[(k4 * 4 + j) * 132 + c] = (&vi.x)[j];
                sWh[(k4 * 4 + j) * 132 + c] = (&vh.x)[j];
            }
        }
    };

    float rg[4][8], zg[4][8];

    // ---- stage r (gate 0) ----
    loadW(0);
    __syncthreads();
    {
        float bi[8];
#pragma unroll
        for (int j = 0; j < 8; j++)
            bi[j] = __ldg(b_ih + 0 * H + c0 + j) + __ldg(b_hh + 0 * H + c0 + j);
        float acc[4][8];
#pragma unroll
        for (int i = 0; i < 4; i++)
#pragma unroll
            for (int j = 0; j < 8; j++) acc[i][j] = bi[j];
#pragma unroll 4
        for (int k = 0; k < 128; k++) {
            float4 a = *(const float4*)&sA[k * 68 + r0];
            float4 hh = *(const float4*)&sHt[k * 68 + r0];
            float4 wi0 = *(const float4*)&sWi[k * 132 + c0];
            float4 wi1 = *(const float4*)&sWi[k * 132 + c0 + 4];
            float4 wh0 = *(const float4*)&sWh[k * 132 + c0];
            float4 wh1 = *(const float4*)&sWh[k * 132 + c0 + 4];
            float av[4] = {a.x, a.y, a.z, a.w};
            float hv[4] = {hh.x, hh.y, hh.z, hh.w};
            float wiv[8] = {wi0.x, wi0.y, wi0.z, wi0.w, wi1.x, wi1.y, wi1.z, wi1.w};
            float whv[8] = {wh0.x, wh0.y, wh0.z, wh0.w, wh1.x, wh1.y, wh1.z, wh1.w};
#pragma unroll
            for (int i = 0; i < 4; i++)
#pragma unroll
                for (int j = 0; j < 8; j++)
                    acc[i][j] += av[i] * wiv[j] + hv[i] * whv[j];
        }
#pragma unroll
        for (int i = 0; i < 4; i++)
#pragma unroll
            for (int j = 0; j < 8; j++)
                rg[i][j] = 1.f / (1.f + __expf(-acc[i][j]));
    }
    __syncthreads();

    // ---- stage z (gate 1) ----
    loadW(1);
    __syncthreads();
    {
        float bi[8];
#pragma unroll
        for (int j = 0; j < 8; j++)
            bi[j] = __ldg(b_ih + 1 * H + c0 + j) + __ldg(b_hh + 1 * H + c0 + j);
        float acc[4][8];
#pragma unroll
        for (int i = 0; i < 4; i++)
#pragma unroll
            for (int j = 0; j < 8; j++) acc[i][j] = bi[j];
#pragma unroll 4
        for (int k = 0; k < 128; k++) {
            float4 a = *(const float4*)&sA[k * 68 + r0];
            float4 hh = *(const float4*)&sHt[k * 68 + r0];
            float4 wi0 = *(const float4*)&sWi[k * 132 + c0];
            float4 wi1 = *(const float4*)&sWi[k * 132 + c0 + 4];
            float4 wh0 = *(const float4*)&sWh[k * 132 + c0];
            float4 wh1 = *(const float4*)&sWh[k * 132 + c0 + 4];
            float av[4] = {a.x, a.y, a.z, a.w};
            float hv[4] = {hh.x, hh.y, hh.z, hh.w};
            float wiv[8] = {wi0.x, wi0.y, wi0.z, wi0.w, wi1.x, wi1.y, wi1.z, wi1.w};
            float whv[8] = {wh0.x, wh0.y, wh0.z, wh0.w, wh1.x, wh1.y, wh1.z, wh1.w};
#pragma unroll
            for (int i = 0; i < 4; i++)
#pragma unroll
                for (int j = 0; j < 8; j++)
                    acc[i][j] += av[i] * wiv[j] + hv[i] * whv[j];
        }
#pragma unroll
        for (int i = 0; i < 4; i++)
#pragma unroll
            for (int j = 0; j < 8; j++)
                zg[i][j] = 1.f / (1.f + __expf(-acc[i][j]));
    }
    __syncthreads();

    // ---- stage n (gate 2) + combine ----
    loadW(2);
    __syncthreads();
    {
        float bii[8], bhh[8];
#pragma unroll
        for (int j = 0; j < 8; j++) {
            bii[j] = __ldg(b_ih + 2 * H + c0 + j);
            bhh[j] = __ldg(b_hh + 2 * H + c0 + j);
        }
        float ai[4][8], ah[4][8];
#pragma unroll
        for (int i = 0; i < 4; i++)
#pragma unroll
            for (int j = 0; j < 8; j++) { ai[i][j] = bii[j]; ah[i][j] = bhh[j]; }
#pragma unroll 4
        for (int k = 0; k < 128; k++) {
            float4 a = *(const float4*)&sA[k * 68 + r0];
            float4 hh = *(const float4*)&sHt[k * 68 + r0];
            float4 wi0 = *(const float4*)&sWi[k * 132 + c0];
            float4 wi1 = *(const float4*)&sWi[k * 132 + c0 + 4];
            float4 wh0 = *(const float4*)&sWh[k * 132 + c0];
            float4 wh1 = *(const float4*)&sWh[k * 132 + c0 + 4];
            float av[4] = {a.x, a.y, a.z, a.w};
            float hv[4] = {hh.x, hh.y, hh.z, hh.w};
            float wiv[8] = {wi0.x, wi0.y, wi0.z, wi0.w, wi1.x, wi1.y, wi1.z, wi1.w};
            float whv[8] = {wh0.x, wh0.y, wh0.z, wh0.w, wh1.x, wh1.y, wh1.z, wh1.w};
#pragma unroll
            for (int i = 0; i < 4; i++)
#pragma unroll
                for (int j = 0; j < 8; j++) {
                    ai[i][j] += av[i] * wiv[j];
                    ah[i][j] += hv[i] * whv[j];
                }
        }
#pragma unroll
        for (int i = 0; i < 4; i++) {
            int r = row0 + r0 + i;
            if (r < nrows) {
                float o[8];
#pragma unroll
                for (int j = 0; j < 8; j++) {
                    float n = tanhf(ai[i][j] + rg[i][j] * ah[i][j]);
                    float hv = sHt[(c0 + j) * 68 + (r0 + i)];
                    o[j] = (1.f - zg[i][j]) * n + zg[i][j] * hv;
                }
                *(float4*)(hout + (size_t)r * H + c0) =
                    make_float4(o[0], o[1], o[2], o[3]);
                *(float4*)(hout + (size_t)r * H + c0 + 4) =
                    make_float4(o[4], o[5], o[6], o[7]);
            }
        }
    }
}

// ---------------- pooling ---------------------------------------------------
__global__ void pool_zero_kernel() {
    for (int i = threadIdx.x; i < NG * H; i += 256) d_gsum[i] = 0.f;
    if (threadIdx.x < NG) d_gcnt[threadIdx.x] = 0.f;
}

// batch is sorted -> run-length local accumulation, few atomics per block
// batch delivered by the harness as int32.
__global__ __launch_bounds__(128) void pool_acc_kernel(
    const int* __restrict__ batch, int nrows) {
    int n0 = blockIdx.x * 128;
    if (n0 >= nrows) return;
    int n1 = n0 + 128;
    if (n1 > nrows) n1 = nrows;
    int c = threadIdx.x;
    int cur = __ldg(batch + n0);
    float acc = 0.f;
    int cnt = 0;
    for (int n = n0; n < n1; n++) {
        int g = __ldg(batch + n);
        if (g != cur) {
            atomicAdd(&d_gsum[cur * H + c], acc);
            if (c == 0) atomicAdd(&d_gcnt[cur], (float)cnt);
            acc = 0.f; cnt = 0; cur = g;
        }
        float v = __ldg(d_hB + (size_t)n * H + c);
        acc += fmaxf(v, 0.f);
        cnt++;
    }
    atomicAdd(&d_gsum[cur * H + c], acc);
    if (c == 0) atomicAdd(&d_gcnt[cur], (float)cnt);
}

__global__ void pool_fin_kernel(float* __restrict__ out) {
    int i = blockIdx.x * 256 + threadIdx.x;
    if (i < NG * H) {
        float cnt = d_gcnt[i >> 7];
        out[i] = d_gsum[i] / fmaxf(cnt, 1.f);
    }
}

// ---------------- launch -----------------------------------------------------
extern "C" void kernel_launch(void* const* d_in, const int* in_sizes, int n_in,
                              void* d_out, int out_size) {
    const float* x      = (const float*)d_in[0];
    const int* ei       = (const int*)d_in[1];
    const int* batch    = (const int*)d_in[2];
    const float* weight = (const float*)d_in[3];
    const float* w_ih   = (const float*)d_in[4];
    const float* w_hh   = (const float*)d_in[5];
    const float* b_ih   = (const float*)d_in[6];
    const float* b_hh   = (const float*)d_in[7];

    int N = in_sizes[0] / H;   // 100000
    int E = in_sizes[1] / 2;   // 1600000

    const int SMEM_MG  = (128 * 68 + 128 * 132) * 4;         // 100 KB
    const int SMEM_GRU = (2 * 128 * 68 + 2 * 128 * 132) * 4; // 200 KB
    cudaFuncSetAttribute(mgemm_kernel,
                         cudaFuncAttributeMaxDynamicSharedMemorySize, SMEM_MG);
    cudaFuncSetAttribute(gru_kernel,
                         cudaFuncAttributeMaxDynamicSharedMemorySize, SMEM_GRU);

    int gblocks = (N + 63) / 64;

    for (int s = 0; s < 4; s++) {
        int hin  = (s == 0) ? 0 : ((s & 1) ? 1 : 2);
        int hout = (s & 1) ? 2 : 1;
        zero_aggr_kernel<<<NN * H / 4 / 256, 256>>>();
        mgemm_kernel<<<gblocks, 256, SMEM_MG>>>(x, hin,
                                                weight + (size_t)s * H * H, N);
        scatter_kernel<<<(E + 7) / 8, 256>>>(ei, E);
        gru_kernel<<<gblocks, 256, SMEM_GRU>>>(x, hin, hout,
                                               w_ih, w_hh, b_ih, b_hh, N);
    }
    pool_zero_kernel<<<1, 256>>>();
    pool_acc_kernel<<<(N + 127) / 128, 128>>>(batch, N);
    pool_fin_kernel<<<(NG * H + 255) / 256, 256>>>((float*)d_out);
}

// round 5
// speedup vs baseline: 1.5093x; 1.5093x over previous
#include <cuda_runtime.h>

#define H 128
#define NN 100000
#define NG 64

// ---------------- scratch (static device allocations; no runtime alloc) ----
__device__ __align__(16) float d_m[(size_t)NN * H];     // message GEMM output
__device__ __align__(16) float d_aggr[(size_t)NN * H];  // scatter-add accumulator
__device__ __align__(16) float d_hA[(size_t)NN * H];    // ping
__device__ __align__(16) float d_hB[(size_t)NN * H];    // pong
__device__ __align__(16) float d_gsum[NG * H];
__device__ float d_gcnt[NG];

__device__ __forceinline__ const float* pick_in(int sel, const float* x) {
    return sel == 0 ? x : (sel == 1 ? (const float*)d_hA : (const float*)d_hB);
}

__device__ __forceinline__ float tanha(float x) {
    float y;
    asm("tanh.approx.f32 %0, %1;" : "=f"(y) : "f"(x));
    return y;
}

// ---------------- zero the aggregation buffer ------------------------------
__global__ void zero_aggr_kernel() {
    int i = blockIdx.x * blockDim.x + threadIdx.x;  // exact: NN*H/4 elements
    ((float4*)d_aggr)[i] = make_float4(0.f, 0.f, 0.f, 0.f);
}

// ---------------- m = h @ W  ([N,128] x [128,128]) -------------------------
__global__ __launch_bounds__(256) void mgemm_kernel(
    const float* __restrict__ x, int hsel,
    const float* __restrict__ W, int nrows) {
    extern __shared__ float smem[];
    float* sH = smem;             // 128 x 68
    float* sW = smem + 128 * 68;  // 128 x 132

    const float* hin = pick_in(hsel, x);
    int t = threadIdx.x;
    int row0 = blockIdx.x * 64;

    for (int i = t; i < 64 * 32; i += 256) {
        int r = i >> 5, k4 = i & 31;
        float4 v = make_float4(0.f, 0.f, 0.f, 0.f);
        if (row0 + r < nrows)
            v = *(const float4*)(hin + (size_t)(row0 + r) * H + k4 * 4);
        sH[(k4 * 4 + 0) * 68 + r] = v.x;
        sH[(k4 * 4 + 1) * 68 + r] = v.y;
        sH[(k4 * 4 + 2) * 68 + r] = v.z;
        sH[(k4 * 4 + 3) * 68 + r] = v.w;
    }
    for (int i = t; i < 128 * 32; i += 256) {
        int k = i >> 5, c4 = i & 31;
        float4 v = *(const float4*)(W + (size_t)k * H + c4 * 4);
        *(float4*)&sW[k * 132 + c4 * 4] = v;
    }
    __syncthreads();

    int tr = t >> 4, tc = t & 15;
    int r0 = tr * 4, c0 = tc * 8;
    float acc[4][8];
#pragma unroll
    for (int i = 0; i < 4; i++)
#pragma unroll
        for (int j = 0; j < 8; j++) acc[i][j] = 0.f;

#pragma unroll 4
    for (int k = 0; k < 128; k++) {
        float4 a = *(const float4*)&sH[k * 68 + r0];
        float4 b0 = *(const float4*)&sW[k * 132 + c0];
        float4 b1 = *(const float4*)&sW[k * 132 + c0 + 4];
        float av[4] = {a.x, a.y, a.z, a.w};
        float bv[8] = {b0.x, b0.y, b0.z, b0.w, b1.x, b1.y, b1.z, b1.w};
#pragma unroll
        for (int i = 0; i < 4; i++)
#pragma unroll
            for (int j = 0; j < 8; j++) acc[i][j] += av[i] * bv[j];
    }

#pragma unroll
    for (int i = 0; i < 4; i++) {
        int r = row0 + r0 + i;
        if (r < nrows) {
            *(float4*)(d_m + (size_t)r * H + c0) =
                make_float4(acc[i][0], acc[i][1], acc[i][2], acc[i][3]);
            *(float4*)(d_m + (size_t)r * H + c0 + 4) =
                make_float4(acc[i][4], acc[i][5], acc[i][6], acc[i][7]);
        }
    }
}

// ---------------- scatter-add: aggr[dst] += m[src] -------------------------
__global__ __launch_bounds__(256) void scatter_kernel(
    const int* __restrict__ ei, int E) {
    int gw = (blockIdx.x * 256 + threadIdx.x) >> 5;
    if (gw >= E) return;
    int lane = threadIdx.x & 31;
    int s = __ldg(ei + gw);
    int d = __ldg(ei + E + gw);
    float4 v = *((const float4*)(d_m + (size_t)s * H) + lane);
    float4* p = (float4*)(d_aggr + (size_t)d * H) + lane;
    asm volatile("red.global.add.v4.f32 [%0], {%1,%2,%3,%4};"
                 :: "l"(p), "f"(v.x), "f"(v.y), "f"(v.z), "f"(v.w)
                 : "memory");
}

// ---------------- fused single-pass GRU cell -------------------------------
// 64-row block, 256 threads, per-thread tile R=8 rows x C=4 cols.
// 4 accumulator sets (r, z, i_n, h_n) computed in ONE pass over k.
// Weights streamed through smem in 4 chunks of K=32 (all 3 gates at once).
#define PA 68    // A/H smem pitch
#define PW 388   // weight smem pitch

__device__ __forceinline__ int wswz(int k, int c) {
    // XOR swizzle on c-bits [2:5) keyed by k to kill STS bank conflicts
    return k * PW + (c ^ (((k >> 2) & 7) << 2));
}

__global__ __launch_bounds__(256) void gru_kernel(
    const float* __restrict__ x, int hinsel, int houtsel,
    const float* __restrict__ w_ih, const float* __restrict__ w_hh,
    const float* __restrict__ b_ih, const float* __restrict__ b_hh,
    int nrows) {
    extern __shared__ float smem[];
    float* sA  = smem;                 // 128 x PA (aggr^T)
    float* sHt = smem + 128 * PA;      // 128 x PA (h^T)
    float* sWi = smem + 2 * 128 * PA;  // 32 x PW  (w_ih chunk, [k][c], c in [0,384))
    float* sWh = sWi + 32 * PW;        // 32 x PW

    const float* hin = pick_in(hinsel, x);
    float* hout = (houtsel == 1) ? d_hA : d_hB;

    int t = threadIdx.x;
    int row0 = blockIdx.x * 64;

    // stage aggr + h transposed: sA[k][r], sHt[k][r]
    for (int i = t; i < 64 * 32; i += 256) {
        int r = i >> 5, k4 = i & 31;
        float4 va = make_float4(0.f, 0.f, 0.f, 0.f), vh = va;
        if (row0 + r < nrows) {
            va = *(const float4*)(d_aggr + (size_t)(row0 + r) * H + k4 * 4);
            vh = *(const float4*)(hin + (size_t)(row0 + r) * H + k4 * 4);
        }
#pragma unroll
        for (int j = 0; j < 4; j++) {
            sA[(k4 * 4 + j) * PA + r]  = (&va.x)[j];
            sHt[(k4 * 4 + j) * PA + r] = (&vh.x)[j];
        }
    }

    int tc = t & 31, tr = t >> 5;       // tr constant per warp -> A/H broadcast
    int c0 = tc * 4, r0 = tr * 8;

    // accumulators, initialized with biases
    float accR[8][4], accZ[8][4], accIN[8][4], accHN[8][4];
    {
        float bR[4], bZ[4], bIN[4], bHN[4];
#pragma unroll
        for (int j = 0; j < 4; j++) {
            bR[j]  = __ldg(b_ih + c0 + j) + __ldg(b_hh + c0 + j);
            bZ[j]  = __ldg(b_ih + H + c0 + j) + __ldg(b_hh + H + c0 + j);
            bIN[j] = __ldg(b_ih + 2 * H + c0 + j);
            bHN[j] = __ldg(b_hh + 2 * H + c0 + j);
        }
#pragma unroll
        for (int i = 0; i < 8; i++)
#pragma unroll
            for (int j = 0; j < 4; j++) {
                accR[i][j] = bR[j];
                accZ[i][j] = bZ[j];
                accIN[i][j] = bIN[j];
                accHN[i][j] = bHN[j];
            }
    }

    for (int kc = 0; kc < 4; kc++) {
        __syncthreads();  // prev compute done (and A/H staging on kc==0)
        // load weight chunk: k in [kc*32, kc*32+32), all 384 cols, both mats
        for (int i = t; i < 384 * 8; i += 256) {
            int k4 = i & 7, c = i >> 3;  // coalesced LDG along k
            float4 vi = *(const float4*)(w_ih + (size_t)c * H + kc * 32 + k4 * 4);
            float4 vh = *(const float4*)(w_hh + (size_t)c * H + kc * 32 + k4 * 4);
#pragma unroll
            for (int j = 0; j < 4; j++) {
                sWi[wswz(k4 * 4 + j, c)] = (&vi.x)[j];
                sWh[wswz(k4 * 4 + j, c)] = (&vh.x)[j];
            }
        }
        __syncthreads();

#pragma unroll 2
        for (int k = 0; k < 32; k++) {
            int ka = kc * 32 + k;
            float4 a0 = *(const float4*)&sA[ka * PA + r0];       // broadcast
            float4 a1 = *(const float4*)&sA[ka * PA + r0 + 4];
            float4 h0 = *(const float4*)&sHt[ka * PA + r0];
            float4 h1 = *(const float4*)&sHt[ka * PA + r0 + 4];
            float4 wiR = *(const float4*)&sWi[wswz(k, c0)];
            float4 wiZ = *(const float4*)&sWi[wswz(k, c0 + 128)];
            float4 wiN = *(const float4*)&sWi[wswz(k, c0 + 256)];
            float4 whR = *(const float4*)&sWh[wswz(k, c0)];
            float4 whZ = *(const float4*)&sWh[wswz(k, c0 + 128)];
            float4 whN = *(const float4*)&sWh[wswz(k, c0 + 256)];

            float av[8] = {a0.x, a0.y, a0.z, a0.w, a1.x, a1.y, a1.z, a1.w};
            float hv[8] = {h0.x, h0.y, h0.z, h0.w, h1.x, h1.y, h1.z, h1.w};
            float wiRv[4] = {wiR.x, wiR.y, wiR.z, wiR.w};
            float wiZv[4] = {wiZ.x, wiZ.y, wiZ.z, wiZ.w};
            float wiNv[4] = {wiN.x, wiN.y, wiN.z, wiN.w};
            float whRv[4] = {whR.x, whR.y, whR.z, whR.w};
            float whZv[4] = {whZ.x, whZ.y, whZ.z, whZ.w};
            float whNv[4] = {whN.x, whN.y, whN.z, whN.w};

#pragma unroll
            for (int i = 0; i < 8; i++)
#pragma unroll
                for (int j = 0; j < 4; j++) {
                    accR[i][j] += av[i] * wiRv[j];
                    accR[i][j] += hv[i] * whRv[j];
                    accZ[i][j] += av[i] * wiZv[j];
                    accZ[i][j] += hv[i] * whZv[j];
                    accIN[i][j] += av[i] * wiNv[j];
                    accHN[i][j] += hv[i] * whNv[j];
                }
        }
    }

    // epilogue: gates + blend (sHt untouched by weight chunks -> no sync needed)
#pragma unroll
    for (int i = 0; i < 8; i++) {
        int r = row0 + r0 + i;
        if (r < nrows) {
            float o[4];
#pragma unroll
            for (int j = 0; j < 4; j++) {
                float rr = 0.5f * tanha(0.5f * accR[i][j]) + 0.5f;  // sigmoid
                float zz = 0.5f * tanha(0.5f * accZ[i][j]) + 0.5f;
                float nn = tanha(accIN[i][j] + rr * accHN[i][j]);
                float hvv = sHt[(c0 + j) * PA + (r0 + i)];
                o[j] = nn + zz * (hvv - nn);
            }
            *(float4*)(hout + (size_t)r * H + c0) =
                make_float4(o[0], o[1], o[2], o[3]);
        }
    }
}

// ---------------- pooling ---------------------------------------------------
__global__ void pool_zero_kernel() {
    for (int i = threadIdx.x; i < NG * H; i += 256) d_gsum[i] = 0.f;
    if (threadIdx.x < NG) d_gcnt[threadIdx.x] = 0.f;
}

__global__ __launch_bounds__(128) void pool_acc_kernel(
    const int* __restrict__ batch, int nrows) {
    int n0 = blockIdx.x * 128;
    if (n0 >= nrows) return;
    int n1 = n0 + 128;
    if (n1 > nrows) n1 = nrows;
    int c = threadIdx.x;
    int cur = __ldg(batch + n0);
    float acc = 0.f;
    int cnt = 0;
    for (int n = n0; n < n1; n++) {
        int g = __ldg(batch + n);
        if (g != cur) {
            atomicAdd(&d_gsum[cur * H + c], acc);
            if (c == 0) atomicAdd(&d_gcnt[cur], (float)cnt);
            acc = 0.f; cnt = 0; cur = g;
        }
        float v = __ldg(d_hB + (size_t)n * H + c);
        acc += fmaxf(v, 0.f);
        cnt++;
    }
    atomicAdd(&d_gsum[cur * H + c], acc);
    if (c == 0) atomicAdd(&d_gcnt[cur], (float)cnt);
}

__global__ void pool_fin_kernel(float* __restrict__ out) {
    int i = blockIdx.x * 256 + threadIdx.x;
    if (i < NG * H) {
        float cnt = d_gcnt[i >> 7];
        out[i] = d_gsum[i] / fmaxf(cnt, 1.f);
    }
}

// ---------------- launch -----------------------------------------------------
extern "C" void kernel_launch(void* const* d_in, const int* in_sizes, int n_in,
                              void* d_out, int out_size) {
    const float* x      = (const float*)d_in[0];
    const int* ei       = (const int*)d_in[1];
    const int* batch    = (const int*)d_in[2];
    const float* weight = (const float*)d_in[3];
    const float* w_ih   = (const float*)d_in[4];
    const float* w_hh   = (const float*)d_in[5];
    const float* b_ih   = (const float*)d_in[6];
    const float* b_hh   = (const float*)d_in[7];

    int N = in_sizes[0] / H;   // 100000
    int E = in_sizes[1] / 2;   // 1600000

    const int SMEM_MG  = (128 * 68 + 128 * 132) * 4;          // 100 KB
    const int SMEM_GRU = (2 * 128 * PA + 2 * 32 * PW) * 4;    // 165 KB
    cudaFuncSetAttribute(mgemm_kernel,
                         cudaFuncAttributeMaxDynamicSharedMemorySize, SMEM_MG);
    cudaFuncSetAttribute(gru_kernel,
                         cudaFuncAttributeMaxDynamicSharedMemorySize, SMEM_GRU);

    int gblocks = (N + 63) / 64;

    for (int s = 0; s < 4; s++) {
        int hin  = (s == 0) ? 0 : ((s & 1) ? 1 : 2);
        int hout = (s & 1) ? 2 : 1;
        zero_aggr_kernel<<<NN * H / 4 / 256, 256>>>();
        mgemm_kernel<<<gblocks, 256, SMEM_MG>>>(x, hin,
                                                weight + (size_t)s * H * H, N);
        scatter_kernel<<<(E + 7) / 8, 256>>>(ei, E);
        gru_kernel<<<gblocks, 256, SMEM_GRU>>>(x, hin, hout,
                                               w_ih, w_hh, b_ih, b_hh, N);
    }
    pool_zero_kernel<<<1, 256>>>();
    pool_acc_kernel<<<(N + 127) / 128, 128>>>(batch, N);
    pool_fin_kernel<<<(NG * H + 255) / 256, 256>>>((float*)d_out);
}